// round 13
// baseline (speedup 1.0000x reference)
#include <cuda_runtime.h>

// Problem constants (from reference)
#define KORD 8
#define NUMI 15
#define GBAS (NUMI + KORD)        // 23 basis functions
#define BB 1024
#define NN 34
#define HH 256
#define WW 256
#define IMG_FLOATS (2 * HH * WW)  // 131072 floats per image
#define CH_STRIDE (HH * WW)
#define IMG_PER_BLK 4
#define NBLK (BB / IMG_PER_BLK)   // 256 blocks
#define TOTAL_F4 (BB * IMG_FLOATS / 4)  // 33554432 float4

// Order-8 B-spline KAN edge via local de Boor: only the K+1=9 basis functions
// covering x are nonzero. Uniform knots (h = 4/15) make every denominator in
// the triangular recurrence a compile-time constant -> pure FFMA, 9 registers.
// Out-of-range x: all reference indicators are zero -> only base*silu survives.
// coef/base point to SHARED memory (staged tables).
__device__ __forceinline__ float spline_apply_one(float x, int id,
                                                  const float* coef,
                                                  const float* base) {
    float res = base[id] * __fdividef(x, 1.0f + __expf(-x));  // base * silu

    const float invh = 15.0f / 4.0f;
    const float g0   = -2.0f - (float)KORD * (4.0f / 15.0f);  // grid[0]

    float u = (x - g0) * invh;                        // position in knot units
    float mf = floorf(u);
    int m = (int)mf;
    if (m < 0 || m > 30) return res;                  // outside knot range
    float t = u - mf;                                 // local coord in [0,1)

    // de Boor: N[r] = B_{m-8+r}(x) after the last iteration
    float N[KORD + 1];
    N[0] = 1.0f;
#pragma unroll
    for (int j = 1; j <= KORD; j++) {
        const float invj = 1.0f / (float)j;           // compile-time constant
        float saved = 0.0f;
#pragma unroll
        for (int r = 0; r < j; r++) {
            float temp = N[r] * invj;
            N[r] = saved + ((float)(r + 1) - t) * temp;
            saved = (t + (float)(j - 1 - r)) * temp;
        }
        N[j] = saved;
    }

    const float* crow = coef + id * GBAS;
#pragma unroll
    for (int r = 0; r <= KORD; r++) {
        int jdx = m - KORD + r;
        if (jdx >= 0 && jdx < GBAS)
            res += crow[jdx] * N[r];
    }
    return res;
}

// Primary: bulk zero-fill, PDL trigger at entry so the scatter secondary can
// launch and run its prologue while the zero wave drains.
__global__ void __launch_bounds__(256)
zero_kernel(float4* __restrict__ out) {
    cudaTriggerProgrammaticLaunchCompletion();
    const float4 z = make_float4(0.f, 0.f, 0.f, 0.f);
    const int stride = gridDim.x * blockDim.x;
#pragma unroll 4
    for (int i = blockIdx.x * blockDim.x + threadIdx.x; i < TOTAL_F4; i += stride)
        out[i] = z;
}

// Secondary (PDL): everything that does not touch `out` — point loads, table
// staging, collision resolution, BOTH spline evaluations — runs before
// cudaGridDependencySynchronize(); only the two 4-byte stores per live point
// execute after the zero kernel completes.
__global__ void __launch_bounds__(256)
scatter_kernel(const float* __restrict__ xv,
               const float* __restrict__ dcoef,
               const float* __restrict__ dbase,
               const float* __restrict__ ccoef,
               const float* __restrict__ cbase,
               float* __restrict__ out) {
    __shared__ float s_dc[34 * GBAS];              // 782 floats
    __shared__ float s_db[34];
    __shared__ float s_cc[5 * GBAS];               // 115 floats
    __shared__ float s_cb[5];
    __shared__ int   s_cx[IMG_PER_BLK][NN];
    __shared__ int   s_cy[IMG_PER_BLK][NN];

    const int tid = threadIdx.x;
    const int sub = tid >> 6;          // image within block (0..3)
    const int n = tid & 63;            // point within image
    const int b = blockIdx.x * IMG_PER_BLK + sub;

    // Per-point direct loads (longest-latency chain head, issued first)
    float power = 0.f; int cx = 0, cy = 0, dev = 0, cat = 0;
    if (n < NN) {
        const float* v = xv + ((size_t)b * NN + n) * 5;
        power = v[0];
        cx = (int)rintf(v[1]);
        cy = (int)rintf(v[2]);
        dev = (int)v[3];
        cat = (int)v[4];
        s_cx[sub][n] = cx;
        s_cy[sub][n] = cy;
    }

    // Table staging (independent loads, overlap the xv latency)
#pragma unroll
    for (int i = tid; i < 34 * GBAS; i += 256) s_dc[i] = dcoef[i];
    if (tid < 34) s_db[tid] = dbase[tid];
    else if (tid >= 64 && tid < 64 + 5 * GBAS) s_cc[tid - 64] = ccoef[tid - 64];
    else if (tid >= 192 && tid < 197) s_cb[tid - 192] = cbase[tid - 192];

    __syncthreads();                   // coords + tables visible

    bool live = (n < NN);
    if (live) {
        // Last-write-wins in index order: dead if any LATER point collides.
        bool dead = false;
#pragma unroll 4
        for (int m = n + 1; m < NN; m++)
            dead |= (s_cx[sub][m] == cx) & (s_cy[sub][m] == cy);
        live = !dead;
    }

    float p = 0.f;
    if (live) {
        p = spline_apply_one(power, dev, s_dc, s_db);
        p = spline_apply_one(p,     cat, s_cc, s_cb);
    }

    // Wait for the zero kernel's writes to be visible, then commit.
    cudaGridDependencySynchronize();

    if (live) {
        const size_t base_off = (size_t)b * IMG_FLOATS;
        const size_t pix = (size_t)cy * WW + cx;
        out[base_off + pix] = p;                  // channel 0
        out[base_off + CH_STRIDE + pix] = power;  // channel 1
    }
}

extern "C" void kernel_launch(void* const* d_in, const int* in_sizes, int n_in,
                              void* d_out, int out_size) {
    const float* xv    = (const float*)d_in[0]; // (1024,34,5)
    const float* dcoef = (const float*)d_in[1]; // (34,23)
    const float* dbase = (const float*)d_in[2]; // (34,)
    const float* ccoef = (const float*)d_in[3]; // (5,23)
    const float* cbase = (const float*)d_in[4]; // (5,)
    float* out = (float*)d_out;                 // (1024,2,256,256)

    // Primary: zero-fill kernel (PDL producer; ~7.0 TB/s).
    zero_kernel<<<4096, 256>>>((float4*)out);

    // Secondary: scatter with programmatic dependent launch — overlaps its
    // prologue (loads + spline compute) with the zero kernel's tail; its
    // stores are ordered by cudaGridDependencySynchronize().
    cudaLaunchConfig_t cfg = {};
    cfg.gridDim = dim3(NBLK, 1, 1);
    cfg.blockDim = dim3(256, 1, 1);
    cfg.dynamicSmemBytes = 0;
    cfg.stream = 0;
    cudaLaunchAttribute attrs[1];
    attrs[0].id = cudaLaunchAttributeProgrammaticStreamSerialization;
    attrs[0].val.programmaticStreamSerializationAllowed = 1;
    cfg.attrs = attrs;
    cfg.numAttrs = 1;
    cudaLaunchKernelEx(&cfg, scatter_kernel, xv, dcoef, dbase, ccoef, cbase, out);
}

// round 14
// speedup vs baseline: 1.0234x; 1.0234x over previous
#include <cuda_runtime.h>

// Problem constants (from reference)
#define KORD 8
#define NUMI 15
#define GBAS (NUMI + KORD)        // 23 basis functions
#define BB 1024
#define NN 34
#define HH 256
#define WW 256
#define IMG_FLOATS (2 * HH * WW)  // 131072 floats per image
#define IMG_F4 (IMG_FLOATS / 4)   // 32768 float4 per image
#define CH_STRIDE (HH * WW)

// Split: memset covers [0, MAIN_IMGS); the fused kernel zeroes + scatters the
// TAIL_IMGS while concurrently scattering the main region.
#define TAIL_IMGS 32
#define MAIN_IMGS (BB - TAIL_IMGS)        // 992
#define IMG_PER_BLK 4
#define SCAT_BLKS (MAIN_IMGS / IMG_PER_BLK)  // 248
#define ZPB 8                              // zero-blocks per tail image
#define ZERO_BLKS (TAIL_IMGS * ZPB)        // 256
#define CHUNK_F4 (IMG_F4 / ZPB)            // 4096 float4 per zero-block

// Monotonic per-tail-image arrival counters. Each replay adds exactly ZPB per
// image; the block seeing (old % ZPB)==ZPB-1 is that replay's winner. No reset
// needed -> re-entrant across graph replays, constant work per call.
__device__ unsigned int g_ctr[TAIL_IMGS];

// Order-8 B-spline KAN edge via local de Boor (uniform knots h=4/15: all
// denominators are compile-time constants -> pure FFMA, 9 registers).
// Out-of-range x: reference indicators all zero -> only base*silu survives.
// coef/base point to SHARED memory.
__device__ __forceinline__ float spline_apply_one(float x, int id,
                                                  const float* coef,
                                                  const float* base) {
    float res = base[id] * __fdividef(x, 1.0f + __expf(-x));  // base * silu

    const float invh = 15.0f / 4.0f;
    const float g0   = -2.0f - (float)KORD * (4.0f / 15.0f);  // grid[0]

    float u = (x - g0) * invh;
    float mf = floorf(u);
    int m = (int)mf;
    if (m < 0 || m > 30) return res;
    float t = u - mf;

    float N[KORD + 1];
    N[0] = 1.0f;
#pragma unroll
    for (int j = 1; j <= KORD; j++) {
        const float invj = 1.0f / (float)j;
        float saved = 0.0f;
#pragma unroll
        for (int r = 0; r < j; r++) {
            float temp = N[r] * invj;
            N[r] = saved + ((float)(r + 1) - t) * temp;
            saved = (t + (float)(j - 1 - r)) * temp;
        }
        N[j] = saved;
    }

    const float* crow = coef + id * GBAS;
#pragma unroll
    for (int r = 0; r <= KORD; r++) {
        int jdx = m - KORD + r;
        if (jdx >= 0 && jdx < GBAS)
            res += crow[jdx] * N[r];
    }
    return res;
}

// Fused kernel, 504 blocks x 256 threads:
//  - blocks [0, SCAT_BLKS): scatter 4 main-region images each (already zeroed
//    by the preceding memset node).
//  - blocks [SCAT_BLKS, +ZERO_BLKS): zero one 16 KB chunk of a tail image;
//    8 blocks per image arrive on a monotonic counter; the last arriver
//    scatters that image (zeros of all 8 blocks visible via fence/atomic).
__global__ void __launch_bounds__(256)
fused_kernel(const float* __restrict__ xv,
             const float* __restrict__ dcoef,
             const float* __restrict__ dbase,
             const float* __restrict__ ccoef,
             const float* __restrict__ cbase,
             float* __restrict__ out) {
    __shared__ float s_dc[34 * GBAS];              // 782 floats
    __shared__ float s_db[34];
    __shared__ float s_cc[5 * GBAS];               // 115 floats
    __shared__ float s_cb[5];
    __shared__ int   s_cx[IMG_PER_BLK][NN];
    __shared__ int   s_cy[IMG_PER_BLK][NN];
    __shared__ int   s_last;

    const int tid = threadIdx.x;
    const int bid = blockIdx.x;

    // ---- Table staging: identical for both roles (3.6 KB, L2-resident) ----
#pragma unroll
    for (int i = tid; i < 34 * GBAS; i += 256) s_dc[i] = dcoef[i];
    if (tid < 34) s_db[tid] = dbase[tid];
    else if (tid >= 64 && tid < 64 + 5 * GBAS) s_cc[tid - 64] = ccoef[tid - 64];
    else if (tid >= 192 && tid < 197) s_cb[tid - 192] = cbase[tid - 192];

    if (bid < SCAT_BLKS) {
        // ================= Scatter role: 4 main-region images =============
        const int sub = tid >> 6;      // image within block (0..3)
        const int n = tid & 63;        // point within image
        const int b = bid * IMG_PER_BLK + sub;

        float power = 0.f; int cx = 0, cy = 0, dev = 0, cat = 0;
        if (n < NN) {
            const float* v = xv + ((size_t)b * NN + n) * 5;
            power = v[0];
            cx = (int)rintf(v[1]);
            cy = (int)rintf(v[2]);
            dev = (int)v[3];
            cat = (int)v[4];
            s_cx[sub][n] = cx;
            s_cy[sub][n] = cy;
        }
        __syncthreads();               // coords + tables visible
        if (n >= NN) return;

        bool dead = false;
#pragma unroll 4
        for (int m = n + 1; m < NN; m++)
            dead |= (s_cx[sub][m] == cx) & (s_cy[sub][m] == cy);
        if (dead) return;

        const size_t base_off = (size_t)b * IMG_FLOATS;
        const size_t pix = (size_t)cy * WW + cx;
        out[base_off + CH_STRIDE + pix] = power;   // ch1 early (no spline)

        float p = spline_apply_one(power, dev, s_dc, s_db);
        p       = spline_apply_one(p,     cat, s_cc, s_cb);
        out[base_off + pix] = p;                   // ch0
    } else {
        // ================= Tail role: zero chunk, maybe scatter ===========
        const int zb = bid - SCAT_BLKS;
        const int ti = zb >> 3;               // tail image index 0..31
        const int chunk = zb & (ZPB - 1);     // eighth within image
        const int b = MAIN_IMGS + ti;

        // Optimistic stage of this image's point data (needed iff winner).
        float power = 0.f; int cx = 0, cy = 0, dev = 0, cat = 0;
        const int n = tid;
        if (n < NN) {
            const float* v = xv + ((size_t)b * NN + n) * 5;
            power = v[0];
            cx = (int)rintf(v[1]);
            cy = (int)rintf(v[2]);
            dev = (int)v[3];
            cat = (int)v[4];
            s_cx[0][n] = cx;
            s_cy[0][n] = cy;
        }

        // Zero my 16 KB chunk (4096 float4, 16 per thread).
        float4* dst = (float4*)out + (size_t)b * IMG_F4 + chunk * CHUNK_F4;
        const float4 z = make_float4(0.f, 0.f, 0.f, 0.f);
#pragma unroll 4
        for (int i = tid; i < CHUNK_F4; i += 256) dst[i] = z;

        __syncthreads();                      // stores issued, smem staged
        if (tid == 0) {
            __threadfence();                  // release my zeros
            unsigned int old = atomicAdd(&g_ctr[ti], 1u);
            s_last = ((old & (ZPB - 1)) == (ZPB - 1)) ? 1 : 0;
        }
        __syncthreads();
        if (!s_last) return;
        __threadfence();                      // acquire all 8 blocks' zeros

        if (n >= NN) return;

        bool dead = false;
#pragma unroll 4
        for (int m = n + 1; m < NN; m++)
            dead |= (s_cx[0][m] == cx) & (s_cy[0][m] == cy);
        if (dead) return;

        const size_t base_off = (size_t)b * IMG_FLOATS;
        const size_t pix = (size_t)cy * WW + cx;
        out[base_off + CH_STRIDE + pix] = power;

        float p = spline_apply_one(power, dev, s_dc, s_db);
        p       = spline_apply_one(p,     cat, s_cc, s_cb);
        out[base_off + pix] = p;
    }
}

extern "C" void kernel_launch(void* const* d_in, const int* in_sizes, int n_in,
                              void* d_out, int out_size) {
    const float* xv    = (const float*)d_in[0]; // (1024,34,5)
    const float* dcoef = (const float*)d_in[1]; // (34,23)
    const float* dbase = (const float*)d_in[2]; // (34,)
    const float* ccoef = (const float*)d_in[3]; // (5,23)
    const float* cbase = (const float*)d_in[4]; // (5,)
    float* out = (float*)d_out;                 // (1024,2,256,256)

    // Phase 1: driver bulk zero of the main region (~7.2 TB/s).
    cudaMemsetAsync(out, 0,
                    (size_t)MAIN_IMGS * IMG_FLOATS * sizeof(float), 0);

    // Phase 2: fused kernel — main-region scatter overlapped with SM-side
    // zero + scatter of the 32-image tail.
    fused_kernel<<<SCAT_BLKS + ZERO_BLKS, 256>>>(xv, dcoef, dbase,
                                                 ccoef, cbase, out);
}